// round 2
// baseline (speedup 1.0000x reference)
#include <cuda_runtime.h>
#include <math.h>

#define S_LEN 512
#define BATCH 64
#define IN_SZ 256
#define HID   1024
#define NCTA  128
#define CPC   8            // columns per CTA = HID/NCTA
#define TPB2  512          // recurrence threads (1 output per thread)

// ---------------- scratch / barrier state (no allocs allowed) ----------------
__device__ float    g_xv[(size_t)S_LEN * BATCH * HID];   // x@V + b + b2
__device__ unsigned g_count = 0;   // barrier arrivals (monotone across replays)
__device__ unsigned g_phase = 0;   // barrier generation (monotone across replays)

// ---------------- split software grid barrier (128 co-resident CTAs) ---------
__device__ __forceinline__ void grid_arrive() {
    // call AFTER __syncthreads(); tid 0 only
    unsigned ticket;
    asm volatile("atom.add.acq_rel.gpu.u32 %0, [%1], 1;"
                 : "=r"(ticket) : "l"(&g_count) : "memory");
    if ((ticket & (NCTA - 1)) == (NCTA - 1)) {
        asm volatile("red.add.release.gpu.u32 [%0], 1;"
                     :: "l"(&g_phase) : "memory");
    }
}
__device__ __forceinline__ void grid_wait(unsigned target) {
    unsigned p;
    do {
        asm volatile("ld.acquire.gpu.u32 %0, [%1];"
                     : "=r"(p) : "l"(&g_phase) : "memory");
    } while ((int)(p - target) < 0);
}

// ---------------- cp.async helpers ----------------
__device__ __forceinline__ void cp_async16(float* smem_dst, const float* gsrc) {
    unsigned s = (unsigned)__cvta_generic_to_shared(smem_dst);
    asm volatile("cp.async.cg.shared.global [%0], [%1], 16;" :: "r"(s), "l"(gsrc));
}
__device__ __forceinline__ void cp_commit() {
    asm volatile("cp.async.commit_group;");
}
template <int N> __device__ __forceinline__ void cp_wait() {
    asm volatile("cp.async.wait_group %0;" :: "n"(N));
}

// =============================================================================
// Phase 1: xv[m][n] = X[m][:] @ V[:][n] + b[n] + b2[n],  M=32768, N=1024, K=256
// =============================================================================
__global__ __launch_bounds__(256)
void xv_gemm(const float* __restrict__ X, const float* __restrict__ V,
             const float* __restrict__ b1, const float* __restrict__ b2) {
    __shared__ float As[16][132];
    __shared__ float Bs[16][132];

    const int tid = threadIdx.x;
    const int m0  = blockIdx.y * 128;
    const int n0  = blockIdx.x * 128;
    const int ty  = tid >> 4;
    const int tx  = tid & 15;

    float acc[8][8];
    #pragma unroll
    for (int i = 0; i < 8; i++)
        #pragma unroll
        for (int j = 0; j < 8; j++) acc[i][j] = 0.f;

    for (int k0 = 0; k0 < IN_SZ; k0 += 16) {
        #pragma unroll
        for (int i = 0; i < 2; i++) {
            int lin = i * 256 + tid;
            int row = lin >> 2, q = lin & 3;
            float4 v = *(const float4*)(X + (size_t)(m0 + row) * IN_SZ + k0 + q * 4);
            As[q * 4 + 0][row] = v.x;
            As[q * 4 + 1][row] = v.y;
            As[q * 4 + 2][row] = v.z;
            As[q * 4 + 3][row] = v.w;
        }
        #pragma unroll
        for (int i = 0; i < 2; i++) {
            int lin  = i * 256 + tid;
            int krow = lin >> 5, c4 = lin & 31;
            *(float4*)&Bs[krow][c4 * 4] =
                *(const float4*)(V + (size_t)(k0 + krow) * HID + n0 + c4 * 4);
        }
        __syncthreads();
        #pragma unroll
        for (int k = 0; k < 16; k++) {
            float a[8], bb[8];
            *(float4*)&a[0]  = *(float4*)&As[k][ty * 8];
            *(float4*)&a[4]  = *(float4*)&As[k][ty * 8 + 4];
            *(float4*)&bb[0] = *(float4*)&Bs[k][tx * 8];
            *(float4*)&bb[4] = *(float4*)&Bs[k][tx * 8 + 4];
            #pragma unroll
            for (int i = 0; i < 8; i++)
                #pragma unroll
                for (int j = 0; j < 8; j++)
                    acc[i][j] = fmaf(a[i], bb[j], acc[i][j]);
        }
        __syncthreads();
    }

    float bsum[8];
    #pragma unroll
    for (int j = 0; j < 8; j++)
        bsum[j] = b1[n0 + tx * 8 + j] + b2[n0 + tx * 8 + j];

    #pragma unroll
    for (int i = 0; i < 8; i++) {
        float* dst = g_xv + (size_t)(m0 + ty * 8 + i) * HID + n0 + tx * 8;
        float4 v0 = make_float4(acc[i][0] + bsum[0], acc[i][1] + bsum[1],
                                acc[i][2] + bsum[2], acc[i][3] + bsum[3]);
        float4 v1 = make_float4(acc[i][4] + bsum[4], acc[i][5] + bsum[5],
                                acc[i][6] + bsum[6], acc[i][7] + bsum[7]);
        *(float4*)dst       = v0;
        *(float4*)(dst + 4) = v1;
    }
}

// =============================================================================
// Phase 2: persistent recurrence, v2.
//   128 CTAs x 512 threads (16 warps, occ 25%).
//   One output per thread: b = tid>>3, c = tid&7.
//   h streamed in 8 chunks of 128 k via cp.async into a 3-buffer ring
//   -> exactly ONE __syncthreads per chunk (ring distance 2 guarantees safety).
//   Split grid barrier: arrive after stores, prefetch next xv, then wait.
// =============================================================================
__global__ __launch_bounds__(TPB2)
void rnn_persistent(const float* __restrict__ W, float* out) {
    extern __shared__ float sm[];
    float* Ws   = sm;                  // [8][1028]
    float* ring = sm + 8 * 1028;       // 3 x [64][132]
    const int BUFS = 64 * 132;         // 8448 floats per buffer

    const int tid   = threadIdx.x;
    const int cbase = blockIdx.x * CPC;
    const int b     = tid >> 3;        // 0..63
    const int c     = tid & 7;         // 0..7

    // Load W slice: warp w (0..15) -> column (w&7), k-half (w>>3)
    {
        int w = tid >> 5, lane = tid & 31;
        int col = w & 7, half = w >> 3;
        const float* src = W + (size_t)(half * 512) * HID + cbase + col;
        float* dst = Ws + col * 1028 + half * 512;
        for (int k = lane; k < 512; k += 32)
            dst[k] = src[(size_t)k * HID];
    }

    __shared__ unsigned s_base;
    if (tid == 0) {
        unsigned p;
        asm volatile("ld.acquire.gpu.u32 %0, [%1];" : "=r"(p) : "l"(&g_phase) : "memory");
        s_base = p;
    }
    __syncthreads();
    const unsigned base = s_base;

    const float* wcol = Ws + c * 1028;
    const float* hrow = ring + b * 132;

    // xv for step 0 (prefetched; updated at each barrier)
    float xv_cur = g_xv[(size_t)b * HID + cbase + c];

    for (int t = 0; t < S_LEN; t++) {
        float acc = 0.f;

        if (t > 0) {
            const float* prev = out + (size_t)(t - 1) * BATCH * HID;

            // prologue: chunk 0 -> ring buf 0  (4 cp.async per thread)
            #pragma unroll
            for (int i = 0; i < 4; i++) {
                int lin = i * TPB2 + tid;          // 0..2047
                int row = lin >> 5, col4 = lin & 31;
                cp_async16(ring + row * 132 + col4 * 4,
                           prev + (size_t)row * HID + col4 * 4);
            }
            cp_commit();

            int buf = 0;
            #pragma unroll 1
            for (int ch = 0; ch < 8; ch++) {
                if (ch < 7) {
                    int nbuf = (buf == 2) ? 0 : buf + 1;
                    float* nb = ring + nbuf * BUFS;
                    const int nk = (ch + 1) * 128;
                    #pragma unroll
                    for (int i = 0; i < 4; i++) {
                        int lin = i * TPB2 + tid;
                        int row = lin >> 5, col4 = lin & 31;
                        cp_async16(nb + row * 132 + col4 * 4,
                                   prev + (size_t)row * HID + nk + col4 * 4);
                    }
                    cp_commit();
                    cp_wait<1>();          // chunk ch landed
                } else {
                    cp_wait<0>();
                }
                __syncthreads();           // single sync per chunk (ring dist 2)

                const float* H  = hrow + buf * BUFS;
                const float* wp = wcol + ch * 128;
                #pragma unroll
                for (int k4 = 0; k4 < 32; k4++) {
                    float4 h  = *(const float4*)(H  + k4 * 4);
                    float4 wv = *(const float4*)(wp + k4 * 4);
                    acc = fmaf(h.x, wv.x, acc);
                    acc = fmaf(h.y, wv.y, acc);
                    acc = fmaf(h.z, wv.z, acc);
                    acc = fmaf(h.w, wv.w, acc);
                }
                buf = (buf == 2) ? 0 : buf + 1;
            }
        }

        float o = tanhf(acc + xv_cur);

        float* dst = out + (size_t)t * BATCH * HID + (size_t)b * HID + cbase + c;
        *dst = o;
        if (t == S_LEN - 1)
            out[(size_t)S_LEN * BATCH * HID + (size_t)b * HID + cbase + c] = o;

        // ---- split barrier: arrive, prefetch next xv, wait ----
        __syncthreads();                       // all stores of this CTA issued
        if (tid == 0) grid_arrive();

        if (t + 1 < S_LEN)
            xv_cur = g_xv[(size_t)(t + 1) * BATCH * HID + (size_t)b * HID + cbase + c];

        if (tid == 0) grid_wait(base + (unsigned)t + 1u);
        __syncthreads();
    }
}

// =============================================================================
// launch
// =============================================================================
extern "C" void kernel_launch(void* const* d_in, const int* in_sizes, int n_in,
                              void* d_out, int out_size) {
    const float* x  = (const float*)d_in[0];
    const float* V  = (const float*)d_in[1];
    const float* W  = (const float*)d_in[2];
    const float* b  = (const float*)d_in[3];
    const float* b2 = (const float*)d_in[4];
    float* out = (float*)d_out;

    dim3 g1(HID / 128, (S_LEN * BATCH) / 128);
    xv_gemm<<<g1, 256>>>(x, V, b, b2);

    const int smem_bytes = (8 * 1028 + 3 * 64 * 132) * (int)sizeof(float); // 134272
    cudaFuncSetAttribute(rnn_persistent,
                         cudaFuncAttributeMaxDynamicSharedMemorySize, smem_bytes);
    rnn_persistent<<<NCTA, TPB2, smem_bytes>>>(W, out);
}

// round 3
// speedup vs baseline: 1.0059x; 1.0059x over previous
#include <cuda_runtime.h>
#include <math.h>

#define S_LEN 512
#define BATCH 64
#define IN_SZ 256
#define HID   1024
#define NCTA  128
#define CPC   8            // columns per CTA = HID/NCTA
#define TPB2  512          // recurrence threads (1 output per thread)

// ---------------- scratch / barrier state (no allocs allowed) ----------------
__device__ float    g_xv[(size_t)S_LEN * BATCH * HID];   // x@V + b + b2
__device__ unsigned g_count = 0;   // barrier arrivals (monotone across replays)
__device__ unsigned g_phase = 0;   // barrier generation (monotone across replays)

// ---------------- split software grid barrier (128 co-resident CTAs) ---------
__device__ __forceinline__ void grid_arrive() {
    // call AFTER __syncthreads(); tid 0 only
    unsigned ticket;
    asm volatile("atom.add.acq_rel.gpu.u32 %0, [%1], 1;"
                 : "=r"(ticket) : "l"(&g_count) : "memory");
    if ((ticket & (NCTA - 1)) == (NCTA - 1)) {
        asm volatile("red.add.release.gpu.u32 [%0], 1;"
                     :: "l"(&g_phase) : "memory");
    }
}
__device__ __forceinline__ void grid_wait(unsigned target) {
    unsigned p;
    do {
        asm volatile("ld.acquire.gpu.u32 %0, [%1];"
                     : "=r"(p) : "l"(&g_phase) : "memory");
    } while ((int)(p - target) < 0);
}

// ---------------- cp.async helpers ----------------
__device__ __forceinline__ void cp_async16(float* smem_dst, const float* gsrc) {
    unsigned s = (unsigned)__cvta_generic_to_shared(smem_dst);
    asm volatile("cp.async.cg.shared.global [%0], [%1], 16;" :: "r"(s), "l"(gsrc));
}
__device__ __forceinline__ void cp_commit() {
    asm volatile("cp.async.commit_group;");
}
template <int N> __device__ __forceinline__ void cp_wait() {
    asm volatile("cp.async.wait_group %0;" :: "n"(N));
}

// =============================================================================
// Phase 1: xv[m][n] = X[m][:] @ V[:][n] + b[n] + b2[n],  M=32768, N=1024, K=256
// =============================================================================
__global__ __launch_bounds__(256)
void xv_gemm(const float* __restrict__ X, const float* __restrict__ V,
             const float* __restrict__ b1, const float* __restrict__ b2) {
    __shared__ float As[16][132];
    __shared__ float Bs[16][132];

    const int tid = threadIdx.x;
    const int m0  = blockIdx.y * 128;
    const int n0  = blockIdx.x * 128;
    const int ty  = tid >> 4;
    const int tx  = tid & 15;

    float acc[8][8];
    #pragma unroll
    for (int i = 0; i < 8; i++)
        #pragma unroll
        for (int j = 0; j < 8; j++) acc[i][j] = 0.f;

    for (int k0 = 0; k0 < IN_SZ; k0 += 16) {
        #pragma unroll
        for (int i = 0; i < 2; i++) {
            int lin = i * 256 + tid;
            int row = lin >> 2, q = lin & 3;
            float4 v = *(const float4*)(X + (size_t)(m0 + row) * IN_SZ + k0 + q * 4);
            As[q * 4 + 0][row] = v.x;
            As[q * 4 + 1][row] = v.y;
            As[q * 4 + 2][row] = v.z;
            As[q * 4 + 3][row] = v.w;
        }
        #pragma unroll
        for (int i = 0; i < 2; i++) {
            int lin  = i * 256 + tid;
            int krow = lin >> 5, c4 = lin & 31;
            *(float4*)&Bs[krow][c4 * 4] =
                *(const float4*)(V + (size_t)(k0 + krow) * HID + n0 + c4 * 4);
        }
        __syncthreads();
        #pragma unroll
        for (int k = 0; k < 16; k++) {
            float a[8], bb[8];
            *(float4*)&a[0]  = *(float4*)&As[k][ty * 8];
            *(float4*)&a[4]  = *(float4*)&As[k][ty * 8 + 4];
            *(float4*)&bb[0] = *(float4*)&Bs[k][tx * 8];
            *(float4*)&bb[4] = *(float4*)&Bs[k][tx * 8 + 4];
            #pragma unroll
            for (int i = 0; i < 8; i++)
                #pragma unroll
                for (int j = 0; j < 8; j++)
                    acc[i][j] = fmaf(a[i], bb[j], acc[i][j]);
        }
        __syncthreads();
    }

    float bsum[8];
    #pragma unroll
    for (int j = 0; j < 8; j++)
        bsum[j] = b1[n0 + tx * 8 + j] + b2[n0 + tx * 8 + j];

    #pragma unroll
    for (int i = 0; i < 8; i++) {
        float* dst = g_xv + (size_t)(m0 + ty * 8 + i) * HID + n0 + tx * 8;
        float4 v0 = make_float4(acc[i][0] + bsum[0], acc[i][1] + bsum[1],
                                acc[i][2] + bsum[2], acc[i][3] + bsum[3]);
        float4 v1 = make_float4(acc[i][4] + bsum[4], acc[i][5] + bsum[5],
                                acc[i][6] + bsum[6], acc[i][7] + bsum[7]);
        *(float4*)dst       = v0;
        *(float4*)(dst + 4) = v1;
    }
}

// =============================================================================
// Phase 2: persistent recurrence, v2.
//   128 CTAs x 512 threads (16 warps, occ 25%).
//   One output per thread: b = tid>>3, c = tid&7.
//   h streamed in 8 chunks of 128 k via cp.async into a 3-buffer ring
//   -> exactly ONE __syncthreads per chunk (ring distance 2 guarantees safety).
//   Split grid barrier: arrive after stores, prefetch next xv, then wait.
// =============================================================================
__global__ __launch_bounds__(TPB2)
void rnn_persistent(const float* __restrict__ W, float* out) {
    extern __shared__ float sm[];
    float* Ws   = sm;                  // [8][1028]
    float* ring = sm + 8 * 1028;       // 3 x [64][132]
    const int BUFS = 64 * 132;         // 8448 floats per buffer

    const int tid   = threadIdx.x;
    const int cbase = blockIdx.x * CPC;
    const int b     = tid >> 3;        // 0..63
    const int c     = tid & 7;         // 0..7

    // Load W slice: warp w (0..15) -> column (w&7), k-half (w>>3)
    {
        int w = tid >> 5, lane = tid & 31;
        int col = w & 7, half = w >> 3;
        const float* src = W + (size_t)(half * 512) * HID + cbase + col;
        float* dst = Ws + col * 1028 + half * 512;
        for (int k = lane; k < 512; k += 32)
            dst[k] = src[(size_t)k * HID];
    }

    __shared__ unsigned s_base;
    if (tid == 0) {
        unsigned p;
        asm volatile("ld.acquire.gpu.u32 %0, [%1];" : "=r"(p) : "l"(&g_phase) : "memory");
        s_base = p;
    }
    __syncthreads();
    const unsigned base = s_base;

    const float* wcol = Ws + c * 1028;
    const float* hrow = ring + b * 132;

    // xv for step 0 (prefetched; updated at each barrier)
    float xv_cur = g_xv[(size_t)b * HID + cbase + c];

    for (int t = 0; t < S_LEN; t++) {
        float acc = 0.f;

        if (t > 0) {
            const float* prev = out + (size_t)(t - 1) * BATCH * HID;

            // prologue: chunk 0 -> ring buf 0  (4 cp.async per thread)
            #pragma unroll
            for (int i = 0; i < 4; i++) {
                int lin = i * TPB2 + tid;          // 0..2047
                int row = lin >> 5, col4 = lin & 31;
                cp_async16(ring + row * 132 + col4 * 4,
                           prev + (size_t)row * HID + col4 * 4);
            }
            cp_commit();

            int buf = 0;
            #pragma unroll 1
            for (int ch = 0; ch < 8; ch++) {
                if (ch < 7) {
                    int nbuf = (buf == 2) ? 0 : buf + 1;
                    float* nb = ring + nbuf * BUFS;
                    const int nk = (ch + 1) * 128;
                    #pragma unroll
                    for (int i = 0; i < 4; i++) {
                        int lin = i * TPB2 + tid;
                        int row = lin >> 5, col4 = lin & 31;
                        cp_async16(nb + row * 132 + col4 * 4,
                                   prev + (size_t)row * HID + nk + col4 * 4);
                    }
                    cp_commit();
                    cp_wait<1>();          // chunk ch landed
                } else {
                    cp_wait<0>();
                }
                __syncthreads();           // single sync per chunk (ring dist 2)

                const float* H  = hrow + buf * BUFS;
                const float* wp = wcol + ch * 128;
                #pragma unroll
                for (int k4 = 0; k4 < 32; k4++) {
                    float4 h  = *(const float4*)(H  + k4 * 4);
                    float4 wv = *(const float4*)(wp + k4 * 4);
                    acc = fmaf(h.x, wv.x, acc);
                    acc = fmaf(h.y, wv.y, acc);
                    acc = fmaf(h.z, wv.z, acc);
                    acc = fmaf(h.w, wv.w, acc);
                }
                buf = (buf == 2) ? 0 : buf + 1;
            }
        }

        float o = tanhf(acc + xv_cur);

        float* dst = out + (size_t)t * BATCH * HID + (size_t)b * HID + cbase + c;
        *dst = o;
        if (t == S_LEN - 1)
            out[(size_t)S_LEN * BATCH * HID + (size_t)b * HID + cbase + c] = o;

        // ---- split barrier: arrive, prefetch next xv, wait ----
        __syncthreads();                       // all stores of this CTA issued
        if (tid == 0) grid_arrive();

        if (t + 1 < S_LEN)
            xv_cur = g_xv[(size_t)(t + 1) * BATCH * HID + (size_t)b * HID + cbase + c];

        if (tid == 0) grid_wait(base + (unsigned)t + 1u);
        __syncthreads();
    }
}

// =============================================================================
// launch
// =============================================================================
extern "C" void kernel_launch(void* const* d_in, const int* in_sizes, int n_in,
                              void* d_out, int out_size) {
    const float* x  = (const float*)d_in[0];
    const float* V  = (const float*)d_in[1];
    const float* W  = (const float*)d_in[2];
    const float* b  = (const float*)d_in[3];
    const float* b2 = (const float*)d_in[4];
    float* out = (float*)d_out;

    dim3 g1(HID / 128, (S_LEN * BATCH) / 128);
    xv_gemm<<<g1, 256>>>(x, V, b, b2);

    const int smem_bytes = (8 * 1028 + 3 * 64 * 132) * (int)sizeof(float); // 134272
    cudaFuncSetAttribute(rnn_persistent,
                         cudaFuncAttributeMaxDynamicSharedMemorySize, smem_bytes);
    rnn_persistent<<<NCTA, TPB2, smem_bytes>>>(W, out);
}

// round 4
// speedup vs baseline: 2.2878x; 2.2744x over previous
#include <cuda_runtime.h>
#include <math.h>

#define S_LEN 512
#define BATCH 64
#define IN_SZ 256
#define HID   1024
#define NCTA  128
#define CPC   8            // columns per CTA = HID/NCTA
#define TPB2  256          // recurrence threads: 8 warps

// ---------------- scratch / barrier state (no allocs allowed) ----------------
__device__ float    g_xv[(size_t)S_LEN * BATCH * HID];   // x@V + b + b2
__device__ unsigned g_count = 0;   // barrier arrivals (monotone across replays)
__device__ unsigned g_phase = 0;   // barrier generation (monotone across replays)

// ---------------- split software grid barrier (128 co-resident CTAs) ---------
__device__ __forceinline__ void grid_arrive() {
    unsigned ticket;
    asm volatile("atom.add.acq_rel.gpu.u32 %0, [%1], 1;"
                 : "=r"(ticket) : "l"(&g_count) : "memory");
    if ((ticket & (NCTA - 1)) == (NCTA - 1)) {
        asm volatile("red.add.release.gpu.u32 [%0], 1;"
                     :: "l"(&g_phase) : "memory");
    }
}
__device__ __forceinline__ void grid_wait(unsigned target) {
    unsigned p;
    do {
        asm volatile("ld.acquire.gpu.u32 %0, [%1];"
                     : "=r"(p) : "l"(&g_phase) : "memory");
    } while ((int)(p - target) < 0);
}

// =============================================================================
// Phase 1: xv[m][n] = X[m][:] @ V[:][n] + b[n] + b2[n],  M=32768, N=1024, K=256
// =============================================================================
__global__ __launch_bounds__(256)
void xv_gemm(const float* __restrict__ X, const float* __restrict__ V,
             const float* __restrict__ b1, const float* __restrict__ b2) {
    __shared__ float As[16][132];
    __shared__ float Bs[16][132];

    const int tid = threadIdx.x;
    const int m0  = blockIdx.y * 128;
    const int n0  = blockIdx.x * 128;
    const int ty  = tid >> 4;
    const int tx  = tid & 15;

    float acc[8][8];
    #pragma unroll
    for (int i = 0; i < 8; i++)
        #pragma unroll
        for (int j = 0; j < 8; j++) acc[i][j] = 0.f;

    for (int k0 = 0; k0 < IN_SZ; k0 += 16) {
        #pragma unroll
        for (int i = 0; i < 2; i++) {
            int lin = i * 256 + tid;
            int row = lin >> 2, q = lin & 3;
            float4 v = *(const float4*)(X + (size_t)(m0 + row) * IN_SZ + k0 + q * 4);
            As[q * 4 + 0][row] = v.x;
            As[q * 4 + 1][row] = v.y;
            As[q * 4 + 2][row] = v.z;
            As[q * 4 + 3][row] = v.w;
        }
        #pragma unroll
        for (int i = 0; i < 2; i++) {
            int lin  = i * 256 + tid;
            int krow = lin >> 5, c4 = lin & 31;
            *(float4*)&Bs[krow][c4 * 4] =
                *(const float4*)(V + (size_t)(k0 + krow) * HID + n0 + c4 * 4);
        }
        __syncthreads();
        #pragma unroll
        for (int k = 0; k < 16; k++) {
            float a[8], bb[8];
            *(float4*)&a[0]  = *(float4*)&As[k][ty * 8];
            *(float4*)&a[4]  = *(float4*)&As[k][ty * 8 + 4];
            *(float4*)&bb[0] = *(float4*)&Bs[k][tx * 8];
            *(float4*)&bb[4] = *(float4*)&Bs[k][tx * 8 + 4];
            #pragma unroll
            for (int i = 0; i < 8; i++)
                #pragma unroll
                for (int j = 0; j < 8; j++)
                    acc[i][j] = fmaf(a[i], bb[j], acc[i][j]);
        }
        __syncthreads();
    }

    float bsum[8];
    #pragma unroll
    for (int j = 0; j < 8; j++)
        bsum[j] = b1[n0 + tx * 8 + j] + b2[n0 + tx * 8 + j];

    #pragma unroll
    for (int i = 0; i < 8; i++) {
        float* dst = g_xv + (size_t)(m0 + ty * 8 + i) * HID + n0 + tx * 8;
        float4 v0 = make_float4(acc[i][0] + bsum[0], acc[i][1] + bsum[1],
                                acc[i][2] + bsum[2], acc[i][3] + bsum[3]);
        float4 v1 = make_float4(acc[i][4] + bsum[4], acc[i][5] + bsum[5],
                                acc[i][6] + bsum[6], acc[i][7] + bsum[7]);
        *(float4*)dst       = v0;
        *(float4*)(dst + 4) = v1;
    }
}

// =============================================================================
// Phase 2: persistent recurrence, v3 — register-tiled, k-split, h from L2.
//   128 CTAs x 256 threads (8 warps). CTA owns 8 columns of W (smem, k-major).
//   Thread = (warp b-tile: 8 batch rows) x (all 8 cols) x (lane ks: k-split 32).
//   Per j (8 outer k-blocks of 128): 8 LDS.128 (W) + 8 LDG.128.cg (h, contiguous
//   512B/warp straight from L2) + 256 FFMA. 64 fp32 accumulators per thread.
//   k-split reduced via padded smem transpose (stride 516 -> conflict-free).
// =============================================================================
__global__ __launch_bounds__(TPB2, 1)
void rnn_persistent(const float* __restrict__ W, float* out) {
    extern __shared__ float sm[];
    float* Ws = sm;                  // [8][1024]  column-major slices, k contiguous
    float* Ps = sm + 8 * 1024;       // partials: [32 ks][512 outputs + 4 pad]
    const int PSTR = 516;

    const int tid   = threadIdx.x;
    const int cbase = blockIdx.x * CPC;
    const int ks    = tid & 31;      // lane = k-split index
    const int btile = tid >> 5;      // warp id 0..7 -> batch rows btile*8..+7

    // Load W slice: Ws[c*1024 + k] = W[k*HID + cbase + c]
    for (int i = tid; i < 8 * 1024; i += TPB2) {
        int c = i >> 10, k = i & 1023;
        Ws[i] = W[(size_t)k * HID + cbase + c];
    }

    __shared__ unsigned s_base;
    if (tid == 0) {
        unsigned p;
        asm volatile("ld.acquire.gpu.u32 %0, [%1];" : "=r"(p) : "l"(&g_phase) : "memory");
        s_base = p;
    }
    __syncthreads();
    const unsigned base = s_base;

    // Each thread finalizes outputs o0 = 2*tid and o0+1 (o = b*8 + c)
    const int o0 = 2 * tid;
    const int ob = o0 >> 3, oc = o0 & 7;
    const size_t xv_off = (size_t)ob * HID + cbase + oc;
    float2 xv = *(const float2*)(g_xv + xv_off);

    const float* wbase = Ws + ks * 4;
    const size_t hrow0 = (size_t)btile * 8 * HID + (size_t)ks * 4;

    for (int t = 0; t < S_LEN; t++) {
        float acc[8][8];
        #pragma unroll
        for (int b = 0; b < 8; b++)
            #pragma unroll
            for (int c = 0; c < 8; c++) acc[b][c] = 0.f;

        if (t > 0) {
            const float* prev = out + (size_t)(t - 1) * BATCH * HID + hrow0;
            #pragma unroll 1
            for (int j = 0; j < 8; j++) {
                const int off = j * 128;
                // W operands for this k-block: 8 cols x float4
                float4 w[8];
                #pragma unroll
                for (int c = 0; c < 8; c++)
                    w[c] = *(const float4*)(wbase + c * 1024 + off);
                // h operands: 8 batch rows x float4, straight from L2
                float4 h[8];
                #pragma unroll
                for (int b = 0; b < 8; b++)
                    h[b] = __ldcg((const float4*)(prev + (size_t)b * HID + off));
                #pragma unroll
                for (int b = 0; b < 8; b++) {
                    #pragma unroll
                    for (int c = 0; c < 8; c++) {
                        acc[b][c] = fmaf(h[b].x, w[c].x, acc[b][c]);
                        acc[b][c] = fmaf(h[b].y, w[c].y, acc[b][c]);
                        acc[b][c] = fmaf(h[b].z, w[c].z, acc[b][c]);
                        acc[b][c] = fmaf(h[b].w, w[c].w, acc[b][c]);
                    }
                }
            }
        }

        // ---- k-split reduction via smem transpose ----
        float* prow = Ps + ks * PSTR + btile * 64;   // outputs (btile*8+b)*8+c
        #pragma unroll
        for (int b = 0; b < 8; b++) {
            *(float4*)(prow + b * 8)     = make_float4(acc[b][0], acc[b][1],
                                                       acc[b][2], acc[b][3]);
            *(float4*)(prow + b * 8 + 4) = make_float4(acc[b][4], acc[b][5],
                                                       acc[b][6], acc[b][7]);
        }
        __syncthreads();

        float sx = 0.f, sy = 0.f;
        #pragma unroll
        for (int p = 0; p < 32; p++) {
            float2 v = *(const float2*)(Ps + p * PSTR + o0);
            sx += v.x; sy += v.y;
        }
        float r0 = tanhf(sx + xv.x);
        float r1 = tanhf(sy + xv.y);

        float* dst = out + (size_t)t * BATCH * HID + xv_off;
        *(float2*)dst = make_float2(r0, r1);
        if (t == S_LEN - 1)
            *(float2*)(out + (size_t)S_LEN * BATCH * HID + xv_off) = make_float2(r0, r1);

        // ---- split grid barrier: arrive, prefetch next xv, wait ----
        __syncthreads();                  // stores issued + Ps reads done
        if (tid == 0) grid_arrive();
        if (t + 1 < S_LEN)
            xv = *(const float2*)(g_xv + (size_t)(t + 1) * BATCH * HID + xv_off);
        if (tid == 0) grid_wait(base + (unsigned)t + 1u);
        __syncthreads();
    }
}

// =============================================================================
// launch
// =============================================================================
extern "C" void kernel_launch(void* const* d_in, const int* in_sizes, int n_in,
                              void* d_out, int out_size) {
    const float* x  = (const float*)d_in[0];
    const float* V  = (const float*)d_in[1];
    const float* W  = (const float*)d_in[2];
    const float* b  = (const float*)d_in[3];
    const float* b2 = (const float*)d_in[4];
    float* out = (float*)d_out;

    dim3 g1(HID / 128, (S_LEN * BATCH) / 128);
    xv_gemm<<<g1, 256>>>(x, V, b, b2);

    const int smem_bytes = (8 * 1024 + 32 * 516) * (int)sizeof(float); // 98816
    cudaFuncSetAttribute(rnn_persistent,
                         cudaFuncAttributeMaxDynamicSharedMemorySize, smem_bytes);
    rnn_persistent<<<NCTA, TPB2, smem_bytes>>>(W, out);
}